// round 7
// baseline (speedup 1.0000x reference)
#include <cuda_runtime.h>
#include <cuda_bf16.h>
#include <cstdint>
#include <cstddef>

#define DEVI static __device__ __forceinline__

constexpr int Mdim = 16384;   // B*S
constexpr int Kdim = 4096;    // INTER
constexpr int Ndim = 1024;    // HID
constexpr int BM = 128, BN = 128, BK = 32;   // BK in elements
constexpr int KITERS = Kdim / BK;            // 128
constexpr int ROWB = 80;                     // smem row stride (64B payload + 16B pad)
constexpr int SLOT_BYTES = BM * ROWB;        // 10240
constexpr int BSTAGES = 4;
constexpr int SMEM_BYTES = 2 * SLOT_BYTES + BSTAGES * SLOT_BYTES;  // 61440

// ------------------------- device scratch ----------------------------------
__device__ int g_mx_bits;
__device__ int g_mw_bits;
__device__ __align__(16) __nv_bfloat16 g_wq[(size_t)Ndim * Kdim];  // 8 MB
__device__ __align__(16) float         g_y [(size_t)Mdim * Ndim];  // 64 MB

// ------------------------- helpers -----------------------------------------
DEVI uint32_t smem_u32(const void* p) {
    uint32_t a;
    asm("{ .reg .u64 t; cvta.to.shared.u64 t, %1; cvt.u32.u64 %0, t; }" : "=r"(a) : "l"(p));
    return a;
}
DEVI void cp16(uint32_t d, const void* g) {
    asm volatile("cp.async.cg.shared.global [%0], [%1], 16;" :: "r"(d), "l"(g));
}
DEVI void cp_commit() { asm volatile("cp.async.commit_group;" ::: "memory"); }
template <int N> DEVI void cp_wait() {
    asm volatile("cp.async.wait_group %0;" :: "n"(N) : "memory");
}
DEVI void ldsm_x4(uint32_t* r, uint32_t a) {
    asm volatile("ldmatrix.sync.aligned.m8n8.x4.shared.b16 {%0,%1,%2,%3}, [%4];"
                 : "=r"(r[0]), "=r"(r[1]), "=r"(r[2]), "=r"(r[3]) : "r"(a));
}
DEVI void mma16816(float* d, const uint32_t* a, const uint32_t* b) {
    asm volatile(
        "mma.sync.aligned.m16n8k16.row.col.f32.bf16.bf16.f32 "
        "{%0,%1,%2,%3}, {%4,%5,%6,%7}, {%8,%9}, {%0,%1,%2,%3};"
        : "+f"(d[0]), "+f"(d[1]), "+f"(d[2]), "+f"(d[3])
        : "r"(a[0]), "r"(a[1]), "r"(a[2]), "r"(a[3]), "r"(b[0]), "r"(b[1]));
}

DEVI float qlevel(float v, float s) {
    v = fminf(fmaxf(v, -2.5f), 2.5f);
    return rintf(v * s);   // integer in [-127,127], exact in bf16
}
DEVI uint32_t packq(float a, float b, float s) {
    __nv_bfloat162 h = __floats2bfloat162_rn(qlevel(a, s), qlevel(b, s));
    return *(uint32_t*)&h;
}

// ------------------------- small kernels -----------------------------------
__global__ void init_kernel() { g_mx_bits = 0; g_mw_bits = 0; }

__global__ void absmax_kernel(const float4* __restrict__ p, size_t n4, int* dst) {
    __shared__ float red[8];
    float m = 0.f;
    for (size_t i = (size_t)blockIdx.x * blockDim.x + threadIdx.x; i < n4;
         i += (size_t)gridDim.x * blockDim.x) {
        float4 v = p[i];
        m = fmaxf(m, fmaxf(fmaxf(fabsf(v.x), fabsf(v.y)), fmaxf(fabsf(v.z), fabsf(v.w))));
    }
    m = fminf(m, 2.5f);
    #pragma unroll
    for (int o = 16; o; o >>= 1) m = fmaxf(m, __shfl_xor_sync(0xffffffffu, m, o));
    if ((threadIdx.x & 31) == 0) red[threadIdx.x >> 5] = m;
    __syncthreads();
    if (threadIdx.x == 0) {
        float t = red[0];
        #pragma unroll
        for (int i = 1; i < 8; i++) t = fmaxf(t, red[i]);
        atomicMax(dst, __float_as_int(t));
    }
}

__global__ void quant_kernel(const float4* __restrict__ src, __nv_bfloat16* __restrict__ dst,
                             size_t n4, const int* mbits) {
    float s = 127.f / __int_as_float(*mbits);
    for (size_t i = (size_t)blockIdx.x * blockDim.x + threadIdx.x; i < n4;
         i += (size_t)gridDim.x * blockDim.x) {
        float4 v = src[i];
        uint2 o;
        o.x = packq(v.x, v.y, s);
        o.y = packq(v.z, v.w, s);
        *(uint2*)&dst[i * 4] = o;
    }
}

// ------------------------- GEMM (bf16 HMMA, fused A-quant) ------------------
// grid (8, 128): x = N tile (W stays L2-resident), y = M tile.
__global__ __launch_bounds__(256) void gemm_kernel(const float* __restrict__ x,
                                                   const float* __restrict__ input,
                                                   const float* __restrict__ bias) {
    extern __shared__ __align__(128) char smem[];
    const uint32_t sbase = smem_u32(smem);

    const int tid = threadIdx.x, wid = tid >> 5, lane = tid & 31;
    const int warp_m = wid >> 2, warp_n = wid & 3;          // 2 x 4 warps
    const int ntile = blockIdx.x, mtile = blockIdx.y;

    const float sx = 127.f / __int_as_float(g_mx_bits);

    // A loader: thread covers row = tid>>1, half = tid&1 (16 fp32 each)
    const int arow = tid >> 1, ahalf = tid & 1;
    const float* Ax = x + (size_t)(mtile * BM + arow) * Kdim + ahalf * 16;
    float4 ar[4];

    auto ldgA = [&](int it) {
        const float* p = Ax + it * BK;
        ar[0] = *(const float4*)(p + 0);
        ar[1] = *(const float4*)(p + 4);
        ar[2] = *(const float4*)(p + 8);
        ar[3] = *(const float4*)(p + 12);
    };
    auto stsA = [&](int it) {
        char* d = smem + (it & 1) * SLOT_BYTES + arow * ROWB + ahalf * 32;
        uint4 v0, v1;
        v0.x = packq(ar[0].x, ar[0].y, sx); v0.y = packq(ar[0].z, ar[0].w, sx);
        v0.z = packq(ar[1].x, ar[1].y, sx); v0.w = packq(ar[1].z, ar[1].w, sx);
        v1.x = packq(ar[2].x, ar[2].y, sx); v1.y = packq(ar[2].z, ar[2].w, sx);
        v1.z = packq(ar[3].x, ar[3].y, sx); v1.w = packq(ar[3].z, ar[3].w, sx);
        *(uint4*)(d + 0)  = v0;
        *(uint4*)(d + 16) = v1;
    };

    // B loader via cp.async
    const __nv_bfloat16* Bg = g_wq + (size_t)ntile * BN * Kdim;
    const int brow = tid >> 2, bseg = (tid & 3) << 4;
    auto issueB = [&](int it) {
        const uint32_t sB = sbase + 2 * SLOT_BYTES + (it & (BSTAGES - 1)) * SLOT_BYTES;
        const size_t koff = (size_t)it * BK;
        #pragma unroll
        for (int u = 0; u < 2; u++) {
            const int row = brow + u * 64;
            cp16(sB + row * ROWB + bseg, (const char*)(Bg + (size_t)row * Kdim + koff) + bseg);
        }
        cp_commit();
    };

    float acc[4][4][4];
    #pragma unroll
    for (int i = 0; i < 4; i++)
        #pragma unroll
        for (int j = 0; j < 4; j++)
            #pragma unroll
            for (int k = 0; k < 4; k++) acc[i][j][k] = 0.f;

    ldgA(0);
    issueB(0); issueB(1); issueB(2);

    const int aRow  = warp_m * 64 + (lane & 15);
    const int aColB = (lane >> 4) << 4;
    const int bRow  = warp_n * 32 + ((lane >> 4) << 3) + (lane & 7);
    const int bColB = ((lane >> 3) & 1) << 4;

    for (int it = 0; it < KITERS; ++it) {
        stsA(it);
        if (it <= KITERS - 3)      cp_wait<2>();
        else if (it == KITERS - 2) cp_wait<1>();
        else                       cp_wait<0>();
        __syncthreads();
        if (it + 3 < KITERS) issueB(it + 3);
        if (it + 1 < KITERS) ldgA(it + 1);

        const uint32_t sA = sbase + (it & 1) * SLOT_BYTES;
        const uint32_t sB = sbase + 2 * SLOT_BYTES + (it & (BSTAGES - 1)) * SLOT_BYTES;

        #pragma unroll
        for (int ks = 0; ks < 2; ks++) {       // two k16 steps per stage
            uint32_t afrag[4][4], bfrag[4][2];
            #pragma unroll
            for (int mi = 0; mi < 4; mi++)
                ldsm_x4(afrag[mi], sA + (aRow + mi * 16) * ROWB + ks * 32 + aColB);
            #pragma unroll
            for (int nj = 0; nj < 2; nj++) {
                uint32_t r[4];
                ldsm_x4(r, sB + (bRow + nj * 16) * ROWB + ks * 32 + bColB);
                bfrag[nj * 2][0]     = r[0]; bfrag[nj * 2][1]     = r[1];
                bfrag[nj * 2 + 1][0] = r[2]; bfrag[nj * 2 + 1][1] = r[3];
            }
            #pragma unroll
            for (int mi = 0; mi < 4; mi++)
                #pragma unroll
                for (int ni = 0; ni < 4; ni++)
                    mma16816(acc[mi][ni], afrag[mi], bfrag[ni]);
        }
    }

    // epilogue: y = acc*invs + bias + residual -> g_y
    const float mx = __int_as_float(g_mx_bits);
    const float mw = __int_as_float(g_mw_bits);
    const float invs = (mx * mw) / (127.f * 127.f);
    const int gq = lane >> 2, t = lane & 3;
    #pragma unroll
    for (int mi = 0; mi < 4; mi++) {
        #pragma unroll
        for (int half = 0; half < 2; half++) {
            const int r = mtile * BM + warp_m * 64 + mi * 16 + gq + half * 8;
            #pragma unroll
            for (int ni = 0; ni < 4; ni++) {
                const int col = ntile * BN + warp_n * 32 + ni * 8 + 2 * t;
                const size_t off = (size_t)r * Ndim + col;
                float2 res;
                res.x = acc[mi][ni][half * 2 + 0] * invs + __ldg(&bias[col])     + __ldg(&input[off]);
                res.y = acc[mi][ni][half * 2 + 1] * invs + __ldg(&bias[col + 1]) + __ldg(&input[off + 1]);
                *(float2*)&g_y[off] = res;
            }
        }
    }
}

// ------------------------- LayerNorm ---------------------------------------
__global__ __launch_bounds__(256) void ln_kernel(const float* __restrict__ gamma,
                                                 const float* __restrict__ beta,
                                                 float* __restrict__ out) {
    __shared__ float red[8];
    const int row = blockIdx.x, tid = threadIdx.x;
    const float4 v = *(const float4*)&g_y[(size_t)row * Ndim + tid * 4];

    float s = v.x + v.y + v.z + v.w;
    #pragma unroll
    for (int o = 16; o; o >>= 1) s += __shfl_xor_sync(0xffffffffu, s, o);
    if ((tid & 31) == 0) red[tid >> 5] = s;
    __syncthreads();
    if (tid < 32) {
        float t = (tid < 8) ? red[tid] : 0.f;
        #pragma unroll
        for (int o = 4; o; o >>= 1) t += __shfl_xor_sync(0xffffffffu, t, o);
        if (tid == 0) red[0] = t;
    }
    __syncthreads();
    const float mu = red[0] * (1.f / Ndim);
    __syncthreads();

    const float dx = v.x - mu, dy = v.y - mu, dz = v.z - mu, dw = v.w - mu;
    float sq = dx * dx + dy * dy + dz * dz + dw * dw;
    #pragma unroll
    for (int o = 16; o; o >>= 1) sq += __shfl_xor_sync(0xffffffffu, sq, o);
    if ((tid & 31) == 0) red[tid >> 5] = sq;
    __syncthreads();
    if (tid < 32) {
        float t = (tid < 8) ? red[tid] : 0.f;
        #pragma unroll
        for (int o = 4; o; o >>= 1) t += __shfl_xor_sync(0xffffffffu, t, o);
        if (tid == 0) red[0] = t;
    }
    __syncthreads();
    const float var = red[0] * (1.f / Ndim);
    const float rstd = rsqrtf(var + 1e-12f);

    const float4 gm = *(const float4*)&gamma[tid * 4];
    const float4 bt = *(const float4*)&beta[tid * 4];
    float4 o4;
    o4.x = gm.x * dx * rstd + bt.x;
    o4.y = gm.y * dy * rstd + bt.y;
    o4.z = gm.z * dz * rstd + bt.z;
    o4.w = gm.w * dw * rstd + bt.w;
    *(float4*)&out[(size_t)row * Ndim + tid * 4] = o4;
}

// ------------------------- launch ------------------------------------------
extern "C" void kernel_launch(void* const* d_in, const int* in_sizes, int n_in,
                              void* d_out, int out_size) {
    const float* x     = (const float*)d_in[0];  // hidden_states [4,4096,4096]
    const float* inp   = (const float*)d_in[1];  // input_tensor  [4,4096,1024]
    const float* W     = (const float*)d_in[2];  // [1024,4096]
    const float* b     = (const float*)d_in[3];
    const float* gamma = (const float*)d_in[4];
    const float* beta  = (const float*)d_in[5];
    float* out = (float*)d_out;

    int* mx; int* mw;
    cudaGetSymbolAddress((void**)&mx, g_mx_bits);
    cudaGetSymbolAddress((void**)&mw, g_mw_bits);
    __nv_bfloat16* wq;
    cudaGetSymbolAddress((void**)&wq, g_wq);

    cudaFuncSetAttribute(gemm_kernel, cudaFuncAttributeMaxDynamicSharedMemorySize, SMEM_BYTES);

    init_kernel<<<1, 1>>>();
    absmax_kernel<<<2048, 256>>>((const float4*)x, (size_t)Mdim * Kdim / 4, mx);
    absmax_kernel<<<256, 256>>>((const float4*)W, (size_t)Ndim * Kdim / 4, mw);
    quant_kernel<<<1024, 256>>>((const float4*)W, wq, (size_t)Ndim * Kdim / 4, mw);
    gemm_kernel<<<dim3(Ndim / BN, Mdim / BM), 256, SMEM_BYTES>>>(x, inp, b);
    ln_kernel<<<Mdim, 256>>>(gamma, beta, out);
}

// round 10
// speedup vs baseline: 1.2698x; 1.2698x over previous
#include <cuda_runtime.h>
#include <cuda_bf16.h>
#include <cstdint>
#include <cstddef>

#define DEVI static __device__ __forceinline__

constexpr int Mdim = 16384;   // B*S
constexpr int Kdim = 4096;    // INTER
constexpr int Ndim = 1024;    // HID
constexpr int BM = 128, BN = 128, BK = 32;   // BK in bf16 elements (64B)
constexpr int KITERS = Kdim / BK;            // 128
constexpr int ROWB = 80;                     // smem row stride (64B payload + 16B pad)
constexpr int STAGES = 2;
constexpr int STAGE_BYTES = 2 * BM * ROWB;   // A + B per stage = 20480
constexpr int SMEM_BYTES = STAGES * STAGE_BYTES;  // 40960

// absmax block split
constexpr int AX_BLOCKS = 2048;
constexpr int AW_BLOCKS = 256;
// quant block split
constexpr int QX_BLOCKS = 8192;
constexpr int QW_BLOCKS = 1024;

// ------------------------- device scratch ----------------------------------
__device__ int g_mx_bits;
__device__ int g_mw_bits;
__device__ __align__(16) __nv_bfloat16 g_xq[(size_t)Mdim * Kdim];  // 128 MB
__device__ __align__(16) __nv_bfloat16 g_wq[(size_t)Ndim * Kdim];  // 8 MB
__device__ __align__(16) float         g_y [(size_t)Mdim * Ndim];  // 64 MB

// ------------------------- helpers -----------------------------------------
DEVI uint32_t smem_u32(const void* p) {
    uint32_t a;
    asm("{ .reg .u64 t; cvta.to.shared.u64 t, %1; cvt.u32.u64 %0, t; }" : "=r"(a) : "l"(p));
    return a;
}
DEVI void cp16(uint32_t d, const void* g) {
    asm volatile("cp.async.cg.shared.global [%0], [%1], 16;" :: "r"(d), "l"(g));
}
DEVI void cp_commit() { asm volatile("cp.async.commit_group;" ::: "memory"); }
template <int N> DEVI void cp_wait() {
    asm volatile("cp.async.wait_group %0;" :: "n"(N) : "memory");
}
DEVI void ldsm_x4(uint32_t* r, uint32_t a) {
    asm volatile("ldmatrix.sync.aligned.m8n8.x4.shared.b16 {%0,%1,%2,%3}, [%4];"
                 : "=r"(r[0]), "=r"(r[1]), "=r"(r[2]), "=r"(r[3]) : "r"(a));
}
DEVI void mma16816(float* d, const uint32_t* a, const uint32_t* b) {
    asm volatile(
        "mma.sync.aligned.m16n8k16.row.col.f32.bf16.bf16.f32 "
        "{%0,%1,%2,%3}, {%4,%5,%6,%7}, {%8,%9}, {%0,%1,%2,%3};"
        : "+f"(d[0]), "+f"(d[1]), "+f"(d[2]), "+f"(d[3])
        : "r"(a[0]), "r"(a[1]), "r"(a[2]), "r"(a[3]), "r"(b[0]), "r"(b[1]));
}

DEVI float qlevel(float v, float s) {
    v = fminf(fmaxf(v, -2.5f), 2.5f);
    return rintf(v * s);   // integer in [-127,127], exact in bf16
}
DEVI uint32_t packq(float a, float b, float s) {
    __nv_bfloat162 h = __floats2bfloat162_rn(qlevel(a, s), qlevel(b, s));
    return *(uint32_t*)&h;
}

// ------------------------- small kernels -----------------------------------
__global__ void init_kernel() { g_mx_bits = 0; g_mw_bits = 0; }

// one kernel covers both tensors: blocks [0,AX_BLOCKS) -> x, rest -> W
__global__ __launch_bounds__(256) void absmax_all_kernel(const float4* __restrict__ x,
                                                         const float4* __restrict__ w) {
    __shared__ float red[8];
    const bool isX = blockIdx.x < AX_BLOCKS;
    const float4* p = isX ? x : w;
    const size_t n4 = isX ? (size_t)Mdim * Kdim / 4 : (size_t)Ndim * Kdim / 4;
    const int nblk  = isX ? AX_BLOCKS : AW_BLOCKS;
    const int bid   = isX ? blockIdx.x : blockIdx.x - AX_BLOCKS;
    int* dst = isX ? &g_mx_bits : &g_mw_bits;

    float m = 0.f;
    for (size_t i = (size_t)bid * blockDim.x + threadIdx.x; i < n4;
         i += (size_t)nblk * blockDim.x) {
        float4 v = p[i];
        m = fmaxf(m, fmaxf(fmaxf(fabsf(v.x), fabsf(v.y)), fmaxf(fabsf(v.z), fabsf(v.w))));
    }
    m = fminf(m, 2.5f);
    #pragma unroll
    for (int o = 16; o; o >>= 1) m = fmaxf(m, __shfl_xor_sync(0xffffffffu, m, o));
    if ((threadIdx.x & 31) == 0) red[threadIdx.x >> 5] = m;
    __syncthreads();
    if (threadIdx.x == 0) {
        float t = red[0];
        #pragma unroll
        for (int i = 1; i < 8; i++) t = fmaxf(t, red[i]);
        atomicMax(dst, __float_as_int(t));
    }
}

// one kernel quantizes both tensors: blocks [0,QX_BLOCKS) -> x, rest -> W
__global__ __launch_bounds__(256) void quant_all_kernel(const float4* __restrict__ x,
                                                        const float4* __restrict__ w) {
    const bool isX = blockIdx.x < QX_BLOCKS;
    const float4* src = isX ? x : w;
    __nv_bfloat16* dst = isX ? g_xq : g_wq;
    const size_t n4 = isX ? (size_t)Mdim * Kdim / 4 : (size_t)Ndim * Kdim / 4;
    const int nblk  = isX ? QX_BLOCKS : QW_BLOCKS;
    const int bid   = isX ? blockIdx.x : blockIdx.x - QX_BLOCKS;
    const float s = 127.f / __int_as_float(isX ? g_mx_bits : g_mw_bits);

    for (size_t i = (size_t)bid * blockDim.x + threadIdx.x; i < n4;
         i += (size_t)nblk * blockDim.x) {
        float4 v = src[i];
        uint2 o;
        o.x = packq(v.x, v.y, s);
        o.y = packq(v.z, v.w, s);
        *(uint2*)&dst[i * 4] = o;
    }
}

// ------------------------- GEMM (bf16 HMMA, proven R3 structure) ------------
// grid (8, 128): x = N tile (W stays L2-resident), y = M tile.
__global__ __launch_bounds__(256) void gemm_kernel(const float* __restrict__ input,
                                                   const float* __restrict__ bias) {
    extern __shared__ __align__(128) char smem[];

    const int tid = threadIdx.x, wid = tid >> 5, lane = tid & 31;
    const int warp_m = wid >> 2, warp_n = wid & 3;          // 2 x 4 warps
    const int ntile = blockIdx.x, mtile = blockIdx.y;

    const __nv_bfloat16* Ag = g_xq + (size_t)mtile * BM * Kdim;
    const __nv_bfloat16* Bg = g_wq + (size_t)ntile * BN * Kdim;

    const int ldrow = tid >> 2, ldseg = (tid & 3) << 4;     // 64 rows/pass, 2 passes

    float acc[4][4][4];
    #pragma unroll
    for (int i = 0; i < 4; i++)
        #pragma unroll
        for (int j = 0; j < 4; j++)
            #pragma unroll
            for (int k = 0; k < 4; k++) acc[i][j][k] = 0.f;

    auto issue = [&](int it) {
        const int slot = it & (STAGES - 1);
        const uint32_t sA = smem_u32(smem + slot * STAGE_BYTES);
        const uint32_t sB = sA + BM * ROWB;
        const size_t koff = (size_t)it * BK;
        #pragma unroll
        for (int u = 0; u < 2; u++) {
            const int row = ldrow + u * 64;
            const size_t g = (size_t)row * Kdim + koff;
            cp16(sA + row * ROWB + ldseg, (const char*)(Ag + g) + ldseg);
            cp16(sB + row * ROWB + ldseg, (const char*)(Bg + g) + ldseg);
        }
        cp_commit();
    };

    issue(0);

    const int aRow  = warp_m * 64 + (lane & 15);
    const int aColB = (lane >> 4) << 4;
    const int bRow  = warp_n * 32 + ((lane >> 4) << 3) + (lane & 7);
    const int bColB = ((lane >> 3) & 1) << 4;

    for (int it = 0; it < KITERS; ++it) {
        if (it + 1 < KITERS) { issue(it + 1); cp_wait<1>(); }
        else                 { cp_wait<0>(); }
        __syncthreads();

        const int slot = it & (STAGES - 1);
        const uint32_t sA = smem_u32(smem + slot * STAGE_BYTES);
        const uint32_t sB = sA + BM * ROWB;

        #pragma unroll
        for (int ks = 0; ks < 2; ks++) {       // two k16 steps per 64B stage
            uint32_t afrag[4][4], bfrag[4][2];
            #pragma unroll
            for (int mi = 0; mi < 4; mi++)
                ldsm_x4(afrag[mi], sA + (aRow + mi * 16) * ROWB + ks * 32 + aColB);
            #pragma unroll
            for (int nj = 0; nj < 2; nj++) {
                uint32_t r[4];
                ldsm_x4(r, sB + (bRow + nj * 16) * ROWB + ks * 32 + bColB);
                bfrag[nj * 2][0]     = r[0]; bfrag[nj * 2][1]     = r[1];
                bfrag[nj * 2 + 1][0] = r[2]; bfrag[nj * 2 + 1][1] = r[3];
            }
            #pragma unroll
            for (int mi = 0; mi < 4; mi++)
                #pragma unroll
                for (int ni = 0; ni < 4; ni++)
                    mma16816(acc[mi][ni], afrag[mi], bfrag[ni]);
        }
        __syncthreads();
    }

    // epilogue: y = acc*invs + bias + residual -> g_y
    const float mx = __int_as_float(g_mx_bits);
    const float mw = __int_as_float(g_mw_bits);
    const float invs = (mx * mw) / (127.f * 127.f);
    const int gq = lane >> 2, t = lane & 3;
    #pragma unroll
    for (int mi = 0; mi < 4; mi++) {
        #pragma unroll
        for (int half = 0; half < 2; half++) {
            const int r = mtile * BM + warp_m * 64 + mi * 16 + gq + half * 8;
            #pragma unroll
            for (int ni = 0; ni < 4; ni++) {
                const int col = ntile * BN + warp_n * 32 + ni * 8 + 2 * t;
                const size_t off = (size_t)r * Ndim + col;
                float2 res;
                res.x = acc[mi][ni][half * 2 + 0] * invs + __ldg(&bias[col])     + __ldg(&input[off]);
                res.y = acc[mi][ni][half * 2 + 1] * invs + __ldg(&bias[col + 1]) + __ldg(&input[off + 1]);
                *(float2*)&g_y[off] = res;
            }
        }
    }
}

// ------------------------- LayerNorm ---------------------------------------
__global__ __launch_bounds__(256) void ln_kernel(const float* __restrict__ gamma,
                                                 const float* __restrict__ beta,
                                                 float* __restrict__ out) {
    __shared__ float red[8];
    const int row = blockIdx.x, tid = threadIdx.x;
    const float4 v = *(const float4*)&g_y[(size_t)row * Ndim + tid * 4];

    float s = v.x + v.y + v.z + v.w;
    #pragma unroll
    for (int o = 16; o; o >>= 1) s += __shfl_xor_sync(0xffffffffu, s, o);
    if ((tid & 31) == 0) red[tid >> 5] = s;
    __syncthreads();
    if (tid < 32) {
        float t = (tid < 8) ? red[tid] : 0.f;
        #pragma unroll
        for (int o = 4; o; o >>= 1) t += __shfl_xor_sync(0xffffffffu, t, o);
        if (tid == 0) red[0] = t;
    }
    __syncthreads();
    const float mu = red[0] * (1.f / Ndim);
    __syncthreads();

    const float dx = v.x - mu, dy = v.y - mu, dz = v.z - mu, dw = v.w - mu;
    float sq = dx * dx + dy * dy + dz * dz + dw * dw;
    #pragma unroll
    for (int o = 16; o; o >>= 1) sq += __shfl_xor_sync(0xffffffffu, sq, o);
    if ((tid & 31) == 0) red[tid >> 5] = sq;
    __syncthreads();
    if (tid < 32) {
        float t = (tid < 8) ? red[tid] : 0.f;
        #pragma unroll
        for (int o = 4; o; o >>= 1) t += __shfl_xor_sync(0xffffffffu, t, o);
        if (tid == 0) red[0] = t;
    }
    __syncthreads();
    const float var = red[0] * (1.f / Ndim);
    const float rstd = rsqrtf(var + 1e-12f);

    const float4 gm = *(const float4*)&gamma[tid * 4];
    const float4 bt = *(const float4*)&beta[tid * 4];
    float4 o4;
    o4.x = gm.x * dx * rstd + bt.x;
    o4.y = gm.y * dy * rstd + bt.y;
    o4.z = gm.z * dz * rstd + bt.z;
    o4.w = gm.w * dw * rstd + bt.w;
    *(float4*)&out[(size_t)row * Ndim + tid * 4] = o4;
}

// ------------------------- launch ------------------------------------------
extern "C" void kernel_launch(void* const* d_in, const int* in_sizes, int n_in,
                              void* d_out, int out_size) {
    const float* x     = (const float*)d_in[0];  // hidden_states [4,4096,4096]
    const float* inp   = (const float*)d_in[1];  // input_tensor  [4,4096,1024]
    const float* W     = (const float*)d_in[2];  // [1024,4096]
    const float* b     = (const float*)d_in[3];
    const float* gamma = (const float*)d_in[4];
    const float* beta  = (const float*)d_in[5];
    float* out = (float*)d_out;

    cudaFuncSetAttribute(gemm_kernel, cudaFuncAttributeMaxDynamicSharedMemorySize, SMEM_BYTES);

    // launch order matters: ncu profiles the 4th launch -> gemm_kernel
    init_kernel<<<1, 1>>>();                                                   // 1
    absmax_all_kernel<<<AX_BLOCKS + AW_BLOCKS, 256>>>((const float4*)x,
                                                      (const float4*)W);       // 2
    quant_all_kernel<<<QX_BLOCKS + QW_BLOCKS, 256>>>((const float4*)x,
                                                     (const float4*)W);        // 3
    gemm_kernel<<<dim3(Ndim / BN, Mdim / BM), 256, SMEM_BYTES>>>(inp, b);      // 4
    ln_kernel<<<Mdim, 256>>>(gamma, beta, out);                                // 5
}